// round 2
// baseline (speedup 1.0000x reference)
#include <cuda_runtime.h>

#define H 512
#define W 512
#define NB 32
#define TILE_H 4

// Warp layout: 32 lanes * 4 px = 128 contiguous pixels in w; 4 warp-columns
// tile the 512-wide row. Each thread computes a 4-wide x 4-tall tile.
// Horizontal halo via warp shuffle (only lanes 0/31 do a scalar load).
__global__ __launch_bounds__(256) void sqdiff_mag_kernel(
    const float* __restrict__ x, float* __restrict__ out)
{
    int gw   = blockIdx.x * 8 + (threadIdx.x >> 5);  // global warp id
    int lane = threadIdx.x & 31;

    int wcol = gw & 3;             // which 128-px column strip
    int rt   = (gw >> 2) & 127;    // row tile (4 rows each)
    int n    = gw >> 9;            // batch

    int wbase = wcol << 7;         // 0,128,256,384
    int wg    = wbase + (lane << 2);
    int h0    = rt * TILE_H;

    const size_t plane = (size_t)H * W;
    const float* g = x + ((size_t)n * 3 + 1) * plane;   // channel 1

    // rows h0-1 .. h0+4, each as cols [wg-1 .. wg+4]
    float r[TILE_H + 2][6];

    #pragma unroll
    for (int j = 0; j < TILE_H + 2; j++) {
        int h = h0 - 1 + j;
        if (h >= 0 && h < H) {
            const float* p = g + (size_t)h * W + wg;
            float4 v = *reinterpret_cast<const float4*>(p);
            r[j][1] = v.x; r[j][2] = v.y; r[j][3] = v.z; r[j][4] = v.w;
            float lft = __shfl_up_sync(0xffffffffu, v.w, 1);
            float rgt = __shfl_down_sync(0xffffffffu, v.x, 1);
            if (lane == 0)  lft = (wbase > 0)       ? __ldg(p - 1) : 0.0f;
            if (lane == 31) rgt = (wbase + 128 < W) ? __ldg(p + 4) : 0.0f;
            r[j][0] = lft; r[j][5] = rgt;
        } else {
            #pragma unroll
            for (int i = 0; i < 6; i++) r[j][i] = 0.0f;
        }
    }

    float* ob = out + (size_t)n * 3 * plane + (size_t)h0 * W + wg;

    #pragma unroll
    for (int rr = 0; rr < TILE_H; rr++) {
        float4 res;
        float* resp = reinterpret_cast<float*>(&res);
        #pragma unroll
        for (int i = 0; i < 4; i++) {
            float c  = r[rr + 1][i + 1];
            float d0 = c - r[rr + 1][i + 2];   // right
            float d1 = c - r[rr + 1][i];       // left
            float d2 = c - r[rr + 2][i + 1];   // down
            float d3 = c - r[rr][i + 1];       // up
            float d4 = c - r[rr + 2][i + 2];   // down-right
            float d5 = c - r[rr + 2][i];       // down-left
            float d6 = c - r[rr][i + 2];       // up-right
            float d7 = c - r[rr][i];           // up-left
            float s = d0 * d0;
            s = fmaf(d1, d1, s);
            s = fmaf(d2, d2, s);
            s = fmaf(d3, d3, s);
            s = fmaf(d4, d4, s);
            s = fmaf(d5, d5, s);
            s = fmaf(d6, d6, s);
            s = fmaf(d7, d7, s);
            resp[i] = sqrtf(s);
        }
        float* o = ob + (size_t)rr * W;
        *reinterpret_cast<float4*>(o)             = res;
        *reinterpret_cast<float4*>(o + plane)     = res;
        *reinterpret_cast<float4*>(o + 2 * plane) = res;
    }
}

extern "C" void kernel_launch(void* const* d_in, const int* in_sizes, int n_in,
                              void* d_out, int out_size)
{
    const float* x = (const float*)d_in[0];
    float* out = (float*)d_out;

    // total warps = 32 batches * 128 row-tiles * 4 col-strips = 16384
    int total_warps = NB * (H / TILE_H) * 4;
    int block = 256;                       // 8 warps
    int grid = total_warps / 8;            // 2048
    sqdiff_mag_kernel<<<grid, block>>>(x, out);
}

// round 3
// speedup vs baseline: 1.2427x; 1.2427x over previous
#include <cuda_runtime.h>

#define H 512
#define W 512
#define NB 32
#define WGROUPS (W / 4)   // 128 float4 groups per row

// R1 structure (1 row x 4px per thread, high occupancy) with the horizontal
// halo delivered by warp shuffle instead of strided scalar LDGs.
// A warp covers 128 contiguous pixels of one row.
__global__ __launch_bounds__(256) void sqdiff_mag_kernel(
    const float* __restrict__ x, float* __restrict__ out)
{
    int idx  = blockIdx.x * blockDim.x + threadIdx.x;
    int lane = threadIdx.x & 31;

    int wg = idx & (WGROUPS - 1);   // float4 group in row
    int t  = idx >> 7;
    int h  = t & (H - 1);
    int n  = t >> 9;
    if (n >= NB) return;

    int w     = wg * 4;
    int wbase = w & ~127;           // start of this warp's 128-px strip

    const size_t plane = (size_t)H * W;
    const float* g = x + ((size_t)n * 3 + 1) * plane;  // channel 1

    float rm[6], rc[6], rp[6];

    // ---- load one row (cols w-1 .. w+4) with shuffle halo ----
    #define LOAD_ROW(dst, hh)                                                  \
    {                                                                          \
        const float* p = g + (size_t)(hh) * W + w;                             \
        float4 v = *reinterpret_cast<const float4*>(p);                        \
        dst[1] = v.x; dst[2] = v.y; dst[3] = v.z; dst[4] = v.w;                \
        float lft = __shfl_up_sync(0xffffffffu, v.w, 1);                       \
        float rgt = __shfl_down_sync(0xffffffffu, v.x, 1);                     \
        /* strip-edge lanes fetch the true neighbor (or 0 at image edge) */    \
        if (lane == 0)  lft = (wbase > 0)       ? __ldg(p - 1) : 0.0f;         \
        if (lane == 31) rgt = (wbase + 128 < W) ? __ldg(p + 4) : 0.0f;         \
        dst[0] = lft; dst[5] = rgt;                                            \
    }

    LOAD_ROW(rc, h)
    if (h > 0) {
        LOAD_ROW(rm, h - 1)
    } else {
        #pragma unroll
        for (int i = 0; i < 6; i++) rm[i] = 0.0f;
    }
    if (h + 1 < H) {
        LOAD_ROW(rp, h + 1)
    } else {
        #pragma unroll
        for (int i = 0; i < 6; i++) rp[i] = 0.0f;
    }
    #undef LOAD_ROW

    float4 res;
    float* resp = reinterpret_cast<float*>(&res);

    #pragma unroll
    for (int i = 0; i < 4; i++) {
        float c  = rc[i + 1];
        float d0 = c - rc[i + 2];
        float d1 = c - rc[i];
        float d2 = c - rp[i + 1];
        float d3 = c - rm[i + 1];
        float d4 = c - rp[i + 2];
        float d5 = c - rp[i];
        float d6 = c - rm[i + 2];
        float d7 = c - rm[i];
        float s = d0 * d0;
        s = fmaf(d1, d1, s);
        s = fmaf(d2, d2, s);
        s = fmaf(d3, d3, s);
        s = fmaf(d4, d4, s);
        s = fmaf(d5, d5, s);
        s = fmaf(d6, d6, s);
        s = fmaf(d7, d7, s);
        resp[i] = sqrtf(s);
    }

    // Streaming stores: evict-first so the input plane stays L2-resident.
    float* ob = out + (size_t)n * 3 * plane + (size_t)h * W + w;
    __stcs(reinterpret_cast<float4*>(ob),             res);
    __stcs(reinterpret_cast<float4*>(ob + plane),     res);
    __stcs(reinterpret_cast<float4*>(ob + 2 * plane), res);
}

extern "C" void kernel_launch(void* const* d_in, const int* in_sizes, int n_in,
                              void* d_out, int out_size)
{
    const float* x = (const float*)d_in[0];
    float* out = (float*)d_out;

    int total_threads = NB * H * WGROUPS;   // 2,097,152
    int block = 256;
    int grid = (total_threads + block - 1) / block;   // 8192
    sqdiff_mag_kernel<<<grid, block>>>(x, out);
}